// round 16
// baseline (speedup 1.0000x reference)
#include <cuda_runtime.h>
#include <cuda_bf16.h>
#include <math.h>
#include <stdint.h>

// Problem constants
#define NN    20000
#define EE    320000
#define ETOT  340000   // EE + NN self loops
#define TT    10
#define BB    4096
#define EMB   128
#define HEADS 4
#define HC    512      // HEADS*EMB
#define LAYERS 2
#define FLATK 2560     // TT * 2 * EMB

// ---------------- device scratch ----------------
__device__ float g_h [NN * HC];        // GAT linear output f32
__device__ float g_s [NN * 8];         // per-node attention scores
__device__ int   g_rowptr[TT * (NN + 1)];
__device__ int   g_wptr  [NN + 1];
__device__ int   g_csr   [TT * ETOT];
__device__ int   g_deg   [NN];
__device__ float g_h1    [BB * EMB];

// bf16 hi/lo split buffers
__device__ __nv_bfloat16 g_embh[TT * NN * EMB], g_embl[TT * NN * EMB];
__device__ __nv_bfloat16 g_yh[NN * HC],  g_yl[NN * HC];
__device__ __nv_bfloat16 g_xh[NN * EMB], g_xl[NN * EMB];
__device__ __nv_bfloat16 g_flath[BB * FLATK], g_flatl[BB * FLATK];
#define WOFF_GAT(br,l) (((br)*2+(l))*65536)
#define WOFF_LIN(br,l) (262144 + ((br)*2+(l))*65536)
#define WOFF_FC1       524288
__device__ __nv_bfloat16 g_wh[851968], g_wl[851968];

// ---------------- fp32 -> bf16 hi/lo split ----------------
__global__ void split_f32(const float* __restrict__ src, __nv_bfloat16* __restrict__ hi,
                          __nv_bfloat16* __restrict__ lo, int n4) {
    int i = blockIdx.x * blockDim.x + threadIdx.x;
    if (i >= n4) return;
    float4 v = ((const float4*)src)[i];
    __nv_bfloat16 h0 = __float2bfloat16(v.x), h1 = __float2bfloat16(v.y);
    __nv_bfloat16 h2 = __float2bfloat16(v.z), h3 = __float2bfloat16(v.w);
    __nv_bfloat16 l0 = __float2bfloat16(v.x - __bfloat162float(h0));
    __nv_bfloat16 l1 = __float2bfloat16(v.y - __bfloat162float(h1));
    __nv_bfloat16 l2 = __float2bfloat16(v.z - __bfloat162float(h2));
    __nv_bfloat16 l3 = __float2bfloat16(v.w - __bfloat162float(h3));
    uint32_t* hp = (uint32_t*)hi;
    uint32_t* lp = (uint32_t*)lo;
    hp[i*2]   = (uint32_t)__bfloat16_as_ushort(h0) | ((uint32_t)__bfloat16_as_ushort(h1) << 16);
    hp[i*2+1] = (uint32_t)__bfloat16_as_ushort(h2) | ((uint32_t)__bfloat16_as_ushort(h3) << 16);
    lp[i*2]   = (uint32_t)__bfloat16_as_ushort(l0) | ((uint32_t)__bfloat16_as_ushort(l1) << 16);
    lp[i*2+1] = (uint32_t)__bfloat16_as_ushort(l2) | ((uint32_t)__bfloat16_as_ushort(l3) << 16);
}

// ============================================================================
// bf16x3 HMMA GEMM, pre-split operands. C = A @ W^T (+bias, +relu).
// A/W as bf16 hi/lo [M,K]/[Ntot,K] row-major. Output f32 OR split bf16.
// Same proven R3 mainloop; BM=BN=128, BK=32, 256 threads.
// ============================================================================
#define BKP 40   // smem row stride in bf16

__device__ __forceinline__ void mma16816(float* c, uint32_t a0, uint32_t a1,
                                         uint32_t a2, uint32_t a3,
                                         uint32_t b0, uint32_t b1) {
    asm volatile(
        "mma.sync.aligned.m16n8k16.row.col.f32.bf16.bf16.f32 "
        "{%0,%1,%2,%3}, {%4,%5,%6,%7}, {%8,%9}, {%0,%1,%2,%3};"
        : "+f"(c[0]), "+f"(c[1]), "+f"(c[2]), "+f"(c[3])
        : "r"(a0), "r"(a1), "r"(a2), "r"(a3), "r"(b0), "r"(b1));
}

__global__ __launch_bounds__(256, 1)
void gemm_pre(const __nv_bfloat16* __restrict__ Aph, const __nv_bfloat16* __restrict__ Apl,
              const __nv_bfloat16* __restrict__ Bph, const __nv_bfloat16* __restrict__ Bpl,
              const float* __restrict__ bias,
              float* __restrict__ Cf, __nv_bfloat16* __restrict__ Ch,
              __nv_bfloat16* __restrict__ Cl,
              int M, int Ntot, int K, int relu)
{
    __shared__ __nv_bfloat16 Ah[128][BKP], Al[128][BKP];
    __shared__ __nv_bfloat16 Bh[128][BKP], Bl[128][BKP];

    const int tid  = threadIdx.x;
    const int warp = tid >> 5;
    const int lane = tid & 31;
    const int g    = lane >> 2;
    const int tg   = lane & 3;
    const int wm   = (warp >> 2) * 64;
    const int wn   = (warp & 3) * 32;
    const int bm   = blockIdx.y * 128;
    const int bn   = blockIdx.x * 128;

    // fill indices: idx covers 512 uint4 slots per array (2 per thread)
    const int fr0 = tid >> 2;          // row for i=0 pass uses idx>>2
    const int fj  = (tid & 3) << 3;    // bf16 col offset 0,8,16,24

    float acc[4][4][4];
#pragma unroll
    for (int mi = 0; mi < 4; mi++)
#pragma unroll
        for (int ni = 0; ni < 4; ni++)
#pragma unroll
            for (int q = 0; q < 4; q++) acc[mi][ni][q] = 0.f;

    const uint4 zero4 = make_uint4(0, 0, 0, 0);

    for (int k0 = 0; k0 < K; k0 += 32) {
#pragma unroll
        for (int i = 0; i < 2; i++) {
            int r = fr0 + (i << 6);    // rows 0..127
            int gr = bm + r;
            uint4 vh = zero4, vl = zero4;
            if (gr < M) {
                vh = *(const uint4*)(Aph + (size_t)gr * K + k0 + fj);
                vl = *(const uint4*)(Apl + (size_t)gr * K + k0 + fj);
            }
            *(uint4*)&Ah[r][fj] = vh;
            *(uint4*)&Al[r][fj] = vl;
            uint4 wh = *(const uint4*)(Bph + (size_t)(bn + r) * K + k0 + fj);
            uint4 wl = *(const uint4*)(Bpl + (size_t)(bn + r) * K + k0 + fj);
            *(uint4*)&Bh[r][fj] = wh;
            *(uint4*)&Bl[r][fj] = wl;
        }
        __syncthreads();

#pragma unroll
        for (int ks = 0; ks < 2; ks++) {
            const int kb = ks * 16;
            uint32_t ah[4][4], al[4][4], bh[4][2], bl[4][2];
#pragma unroll
            for (int mi = 0; mi < 4; mi++) {
                int r = wm + mi * 16;
                ah[mi][0] = *(uint32_t*)&Ah[r + g     ][kb + tg * 2];
                ah[mi][1] = *(uint32_t*)&Ah[r + g + 8 ][kb + tg * 2];
                ah[mi][2] = *(uint32_t*)&Ah[r + g     ][kb + tg * 2 + 8];
                ah[mi][3] = *(uint32_t*)&Ah[r + g + 8 ][kb + tg * 2 + 8];
                al[mi][0] = *(uint32_t*)&Al[r + g     ][kb + tg * 2];
                al[mi][1] = *(uint32_t*)&Al[r + g + 8 ][kb + tg * 2];
                al[mi][2] = *(uint32_t*)&Al[r + g     ][kb + tg * 2 + 8];
                al[mi][3] = *(uint32_t*)&Al[r + g + 8 ][kb + tg * 2 + 8];
            }
#pragma unroll
            for (int ni = 0; ni < 4; ni++) {
                int r = wn + ni * 8 + g;
                bh[ni][0] = *(uint32_t*)&Bh[r][kb + tg * 2];
                bh[ni][1] = *(uint32_t*)&Bh[r][kb + tg * 2 + 8];
                bl[ni][0] = *(uint32_t*)&Bl[r][kb + tg * 2];
                bl[ni][1] = *(uint32_t*)&Bl[r][kb + tg * 2 + 8];
            }
#pragma unroll
            for (int mi = 0; mi < 4; mi++)
#pragma unroll
                for (int ni = 0; ni < 4; ni++) {
                    mma16816(acc[mi][ni], ah[mi][0], ah[mi][1], ah[mi][2], ah[mi][3],
                             bh[ni][0], bh[ni][1]);
                    mma16816(acc[mi][ni], ah[mi][0], ah[mi][1], ah[mi][2], ah[mi][3],
                             bl[ni][0], bl[ni][1]);
                    mma16816(acc[mi][ni], al[mi][0], al[mi][1], al[mi][2], al[mi][3],
                             bh[ni][0], bh[ni][1]);
                }
        }
        __syncthreads();
    }

#pragma unroll
    for (int mi = 0; mi < 4; mi++) {
        int r0 = bm + wm + mi * 16 + g;
        int r1 = r0 + 8;
#pragma unroll
        for (int ni = 0; ni < 4; ni++) {
            int cc = bn + wn + ni * 8 + tg * 2;
            float b0 = 0.f, b1 = 0.f;
            if (bias) { b0 = bias[cc]; b1 = bias[cc + 1]; }
            float2 v0 = make_float2(acc[mi][ni][0] + b0, acc[mi][ni][1] + b1);
            float2 v1 = make_float2(acc[mi][ni][2] + b0, acc[mi][ni][3] + b1);
            if (relu) {
                v0.x = fmaxf(v0.x, 0.f); v0.y = fmaxf(v0.y, 0.f);
                v1.x = fmaxf(v1.x, 0.f); v1.y = fmaxf(v1.y, 0.f);
            }
            if (Cf) {
                if (r0 < M) *(float2*)(Cf + (size_t)r0 * Ntot + cc) = v0;
                if (r1 < M) *(float2*)(Cf + (size_t)r1 * Ntot + cc) = v1;
            } else {
#pragma unroll
                for (int hh = 0; hh < 2; hh++) {
                    float2 v = hh ? v1 : v0;
                    int rr = hh ? r1 : r0;
                    if (rr >= M) continue;
                    __nv_bfloat16 h0 = __float2bfloat16(v.x), h1 = __float2bfloat16(v.y);
                    __nv_bfloat16 l0 = __float2bfloat16(v.x - __bfloat162float(h0));
                    __nv_bfloat16 l1 = __float2bfloat16(v.y - __bfloat162float(h1));
                    *(uint32_t*)(Ch + (size_t)rr * Ntot + cc) =
                        (uint32_t)__bfloat16_as_ushort(h0) | ((uint32_t)__bfloat16_as_ushort(h1) << 16);
                    *(uint32_t*)(Cl + (size_t)rr * Ntot + cc) =
                        (uint32_t)__bfloat16_as_ushort(l0) | ((uint32_t)__bfloat16_as_ushort(l1) << 16);
                }
            }
        }
    }
}

// ---------------- CSR build ----------------
__global__ void init_deg() {
    int i = blockIdx.x * blockDim.x + threadIdx.x;
    if (i < NN) g_deg[i] = 1;
}

__global__ void count_deg(const int* __restrict__ dst) {
    int e = blockIdx.x * blockDim.x + threadIdx.x;
    if (e < EE) atomicAdd(&g_deg[dst[e]], 1);
}

// single-pass scan: 1024 threads x 20 elems each
__global__ void scan_deg(int* __restrict__ rowptr) {
    const int C = 20;
    int tid = threadIdx.x;
    int lane = tid & 31, w = tid >> 5;
    int base = tid * C;
    int loc[C];
    int s = 0;
#pragma unroll
    for (int j = 0; j < C; j++) {
        int idx = base + j;
        int v = (idx < NN) ? g_deg[idx] : 0;
        s += v;
        loc[j] = s;
    }
    int x = s;
#pragma unroll
    for (int off = 1; off < 32; off <<= 1) {
        int t = __shfl_up_sync(0xffffffffu, x, off);
        if (lane >= off) x += t;
    }
    __shared__ int wsum[32];
    if (lane == 31) wsum[w] = x;
    __syncthreads();
    if (w == 0) {
        int y = wsum[lane];
#pragma unroll
        for (int off = 1; off < 32; off <<= 1) {
            int t = __shfl_up_sync(0xffffffffu, y, off);
            if (lane >= off) y += t;
        }
        wsum[lane] = y;
    }
    __syncthreads();
    int offset = x - s + (w > 0 ? wsum[w - 1] : 0);
    if (tid == 0) { rowptr[0] = 0; g_wptr[0] = 0; }
#pragma unroll
    for (int j = 0; j < C; j++) {
        int idx = base + j;
        if (idx < NN) {
            int val = offset + loc[j];
            rowptr[idx + 1] = val;
            g_wptr[idx + 1] = val;
        }
    }
}

__global__ void scatter_edges(const int* __restrict__ src, const int* __restrict__ dst,
                              int* __restrict__ csr) {
    int e = blockIdx.x * blockDim.x + threadIdx.x;
    if (e < EE) {
        int pos = atomicAdd(&g_wptr[dst[e]], 1);
        csr[pos] = src[e];
    }
}

__global__ void scatter_self(int* __restrict__ csr) {
    int n = blockIdx.x * blockDim.x + threadIdx.x;
    if (n < NN) {
        int pos = atomicAdd(&g_wptr[n], 1);
        csr[pos] = n;
    }
}

// ---------------- per-node attention scores ----------------
__global__ void attn_scores(const float* __restrict__ h, const float* __restrict__ as_,
                            const float* __restrict__ ad_) {
    int gwarp = (blockIdx.x * blockDim.x + threadIdx.x) >> 5;
    int lane = threadIdx.x & 31;
    if (gwarp >= NN) return;
    const float* hp = h + (size_t)gwarp * HC;
    float aS[4] = {0.f, 0.f, 0.f, 0.f};
    float aD[4] = {0.f, 0.f, 0.f, 0.f};
#pragma unroll
    for (int i = 0; i < 16; i++) {
        int c = lane + 32 * i;
        float v = hp[c];
        int hh = i >> 2;
        aS[hh] += v * as_[c];
        aD[hh] += v * ad_[c];
    }
#pragma unroll
    for (int hh = 0; hh < 4; hh++) {
#pragma unroll
        for (int off = 16; off; off >>= 1) {
            aS[hh] += __shfl_xor_sync(0xffffffffu, aS[hh], off);
            aD[hh] += __shfl_xor_sync(0xffffffffu, aD[hh], off);
        }
    }
    if (lane == 0) {
        float* sp = g_s + gwarp * 8;
        sp[0] = aS[0]; sp[1] = aS[1]; sp[2] = aS[2]; sp[3] = aS[3];
        sp[4] = aD[0]; sp[5] = aD[1]; sp[6] = aD[2]; sp[7] = aD[3];
    }
}

// ---------------- GAT segment softmax + aggregation (R3 block form) -----------
// Only change vs R3: final store emits bf16 hi/lo split.
__global__ void gat_aggregate(const float* __restrict__ h,
                              const int* __restrict__ rowptr, const int* __restrict__ csr,
                              const float* __restrict__ gbias,
                              __nv_bfloat16* __restrict__ yh, __nv_bfloat16* __restrict__ yl) {
    int d = blockIdx.x;
    int tid = threadIdx.x;
    int start = rowptr[d], end = rowptr[d + 1];

    __shared__ float red[128];
    __shared__ float m[4], invsum[4], sdst[4];
    if (tid < 4) sdst[tid] = g_s[d * 8 + 4 + tid];
    __syncthreads();

    float mx[4] = {-1e30f, -1e30f, -1e30f, -1e30f};
    for (int e = start + tid; e < end; e += 128) {
        int sidx = csr[e];
#pragma unroll
        for (int hh = 0; hh < 4; hh++) {
            float l = g_s[sidx * 8 + hh] + sdst[hh];
            l = l > 0.f ? l : 0.2f * l;
            mx[hh] = fmaxf(mx[hh], l);
        }
    }
#pragma unroll
    for (int hh = 0; hh < 4; hh++) {
        red[tid] = mx[hh];
        __syncthreads();
        for (int off = 64; off; off >>= 1) {
            if (tid < off) red[tid] = fmaxf(red[tid], red[tid + off]);
            __syncthreads();
        }
        if (tid == 0) m[hh] = red[0];
        __syncthreads();
    }

    float sm[4] = {0.f, 0.f, 0.f, 0.f};
    for (int e = start + tid; e < end; e += 128) {
        int sidx = csr[e];
#pragma unroll
        for (int hh = 0; hh < 4; hh++) {
            float l = g_s[sidx * 8 + hh] + sdst[hh];
            l = l > 0.f ? l : 0.2f * l;
            sm[hh] += expf(l - m[hh]);
        }
    }
#pragma unroll
    for (int hh = 0; hh < 4; hh++) {
        red[tid] = sm[hh];
        __syncthreads();
        for (int off = 64; off; off >>= 1) {
            if (tid < off) red[tid] += red[tid + off];
            __syncthreads();
        }
        if (tid == 0) invsum[hh] = 1.f / red[0];
        __syncthreads();
    }

    int head = tid >> 5, lane = tid & 31;
    float mh = m[head], inv = invsum[head], sd = sdst[head];
    float acc0 = 0.f, acc1 = 0.f, acc2 = 0.f, acc3 = 0.f;
    for (int e = start; e < end; e++) {
        int sidx = csr[e];
        float l = g_s[sidx * 8 + head] + sd;
        l = l > 0.f ? l : 0.2f * l;
        float alpha = expf(l - mh) * inv;
        const float* hp = h + (size_t)sidx * HC + head * EMB + lane;
        acc0 += alpha * hp[0];
        acc1 += alpha * hp[32];
        acc2 += alpha * hp[64];
        acc3 += alpha * hp[96];
    }
    int bb = head * EMB + lane;
    size_t ob = (size_t)d * HC + bb;
    float vals[4] = {acc0 + gbias[bb], acc1 + gbias[bb + 32],
                     acc2 + gbias[bb + 64], acc3 + gbias[bb + 96]};
#pragma unroll
    for (int q = 0; q < 4; q++) {
        float v = vals[q];
        __nv_bfloat16 hi = __float2bfloat16(v);
        __nv_bfloat16 lo = __float2bfloat16(v - __bfloat162float(hi));
        yh[ob + q * 32] = hi;
        yl[ob + q * 32] = lo;
    }
}

// ---------------- gather clf rows (bf16) into reversed-time flat layout -------
__global__ void gather_clf(const int* __restrict__ clf, int slot) {
    int idx = blockIdx.x * blockDim.x + threadIdx.x;   // BB*64 uint32 pairs
    if (idx >= BB * 64) return;
    int b = idx >> 6, c2 = idx & 63;
    int node = clf[b];
    uint32_t vh = *(const uint32_t*)(g_xh + (size_t)node * EMB + c2 * 2);
    uint32_t vl = *(const uint32_t*)(g_xl + (size_t)node * EMB + c2 * 2);
    *(uint32_t*)(g_flath + (size_t)b * FLATK + slot + c2 * 2) = vh;
    *(uint32_t*)(g_flatl + (size_t)b * FLATK + slot + c2 * 2) = vl;
}

// ---------------- final fc2 ----------------
__global__ void fc2_kernel(const float* __restrict__ W, const float* __restrict__ bias,
                           float* __restrict__ out) {
    int idx = blockIdx.x * blockDim.x + threadIdx.x;
    if (idx >= BB * 2) return;
    int b = idx >> 1, o = idx & 1;
    const float* hp = g_h1 + (size_t)b * EMB;
    const float* wp = W + o * EMB;
    float acc = bias[o];
#pragma unroll 4
    for (int j = 0; j < EMB; j++) acc += hp[j] * wp[j];
    out[idx] = fmaxf(acc, 0.f);
}

// ---------------- host ----------------
extern "C" void kernel_launch(void* const* d_in, const int* in_sizes, int n_in,
                              void* d_out, int out_size) {
    (void)in_sizes; (void)n_in; (void)out_size;
    const float* emb   = (const float*)d_in[0];
    const int*   edges = (const int*)d_in[1];
    const int*   clf   = (const int*)d_in[5];
    const float* gatW[2] = {(const float*)d_in[6],  (const float*)d_in[12]};
    const float* gas[2]  = {(const float*)d_in[7],  (const float*)d_in[13]};
    const float* gad[2]  = {(const float*)d_in[8],  (const float*)d_in[14]};
    const float* gb[2]   = {(const float*)d_in[9],  (const float*)d_in[15]};
    const float* lW[2]   = {(const float*)d_in[10], (const float*)d_in[16]};
    const float* lb[2]   = {(const float*)d_in[11], (const float*)d_in[17]};
    const float* fc1W = (const float*)d_in[18];
    const float* fc1b = (const float*)d_in[19];
    const float* fc2W = (const float*)d_in[20];
    const float* fc2b = (const float*)d_in[21];

    float *h_, *h1_;
    int *rowptr_, *csr_;
    __nv_bfloat16 *embh_, *embl_, *yh_, *yl_, *xh_, *xl_, *flath_, *flatl_, *wh_, *wl_;
    cudaGetSymbolAddress((void**)&h_,      g_h);
    cudaGetSymbolAddress((void**)&h1_,     g_h1);
    cudaGetSymbolAddress((void**)&rowptr_, g_rowptr);
    cudaGetSymbolAddress((void**)&csr_,    g_csr);
    cudaGetSymbolAddress((void**)&embh_,   g_embh);
    cudaGetSymbolAddress((void**)&embl_,   g_embl);
    cudaGetSymbolAddress((void**)&yh_,     g_yh);
    cudaGetSymbolAddress((void**)&yl_,     g_yl);
    cudaGetSymbolAddress((void**)&xh_,     g_xh);
    cudaGetSymbolAddress((void**)&xl_,     g_xl);
    cudaGetSymbolAddress((void**)&flath_,  g_flath);
    cudaGetSymbolAddress((void**)&flatl_,  g_flatl);
    cudaGetSymbolAddress((void**)&wh_,     g_wh);
    cudaGetSymbolAddress((void**)&wl_,     g_wl);

    auto split = [&](const float* src, __nv_bfloat16* hi, __nv_bfloat16* lo, int n) {
        int n4 = n / 4;
        split_f32<<<(n4 + 255) / 256, 256>>>(src, hi, lo, n4);
    };

    // one-time conversions
    split(emb, embh_, embl_, TT * NN * EMB);
    for (int br = 0; br < 2; br++)
        for (int l = 0; l < LAYERS; l++) {
            split(gatW[br] + (size_t)l * HC * EMB, wh_ + WOFF_GAT(br, l), wl_ + WOFF_GAT(br, l), HC * EMB);
            split(lW[br]   + (size_t)l * EMB * HC, wh_ + WOFF_LIN(br, l), wl_ + WOFF_LIN(br, l), EMB * HC);
        }
    split(fc1W, wh_ + WOFF_FC1, wl_ + WOFF_FC1, EMB * FLATK);

    // build CSR per timestep
    for (int t = 0; t < TT; t++) {
        const int* src = edges + (size_t)t * 2 * EE;
        const int* dst = src + EE;
        init_deg<<<(NN + 255) / 256, 256>>>();
        count_deg<<<(EE + 255) / 256, 256>>>(dst);
        scan_deg<<<1, 1024>>>(rowptr_ + t * (NN + 1));
        scatter_edges<<<(EE + 255) / 256, 256>>>(src, dst, csr_ + (size_t)t * ETOT);
        scatter_self<<<(NN + 255) / 256, 256>>>(csr_ + (size_t)t * ETOT);
    }

    const int MY = (NN + 127) / 128;  // 157
    for (int br = 0; br < 2; br++) {
        for (int t = 0; t < TT; t++) {
            const __nv_bfloat16* ah = embh_ + (size_t)t * NN * EMB;
            const __nv_bfloat16* al = embl_ + (size_t)t * NN * EMB;
            for (int l = 0; l < LAYERS; l++) {
                // h = x @ gatW^T  [N,512] f32
                gemm_pre<<<dim3(HC / 128, MY), 256>>>(
                    ah, al, wh_ + WOFF_GAT(br, l), wl_ + WOFF_GAT(br, l),
                    nullptr, h_, nullptr, nullptr, NN, HC, EMB, 0);
                attn_scores<<<(NN * 32 + 255) / 256, 256>>>(
                    h_, gas[br] + l * HC, gad[br] + l * HC);
                gat_aggregate<<<NN, 128>>>(
                    h_, rowptr_ + t * (NN + 1), csr_ + (size_t)t * ETOT,
                    gb[br] + l * HC, yh_, yl_);
                // x = relu(y @ lW^T + lb) -> bf16 split
                gemm_pre<<<dim3(EMB / 128, MY), 256>>>(
                    yh_, yl_, wh_ + WOFF_LIN(br, l), wl_ + WOFF_LIN(br, l),
                    lb[br] + l * EMB, nullptr, xh_, xl_, NN, EMB, HC, 1);
                ah = xh_; al = xl_;
            }
            gather_clf<<<(BB * 64 + 255) / 256, 256>>>(clf, (TT - 1 - t) * 256 + br * EMB);
        }
    }

    // head MLP
    gemm_pre<<<dim3(1, BB / 128), 256>>>(
        flath_, flatl_, wh_ + WOFF_FC1, wl_ + WOFF_FC1,
        fc1b, h1_, nullptr, nullptr, BB, EMB, FLATK, 1);
    fc2_kernel<<<(BB * 2 + 255) / 256, 256>>>(fc2W, fc2b, (float*)d_out);
}

// round 17
// speedup vs baseline: 1.0023x; 1.0023x over previous
#include <cuda_runtime.h>
#include <cuda_bf16.h>
#include <math.h>
#include <stdint.h>

// Problem constants
#define NN    20000
#define EE    320000
#define ETOT  340000   // EE + NN self loops
#define TT    10
#define BB    4096
#define EMB   128
#define HEADS 4
#define HC    512      // HEADS*EMB
#define LAYERS 2
#define FLATK 2560     // TT * 2 * EMB

// ---------------- device scratch ----------------
__device__ float g_h [NN * HC];        // GAT linear output f32
__device__ float g_s [NN * 8];         // per-node attention scores
__device__ int   g_rowptr[TT * (NN + 1)];
__device__ int   g_wptr  [NN + 1];
__device__ int   g_csr   [TT * ETOT];
__device__ int   g_deg   [NN];
__device__ float g_h1    [BB * EMB];

// bf16 hi/lo split buffers
__device__ __nv_bfloat16 g_embh[TT * NN * EMB], g_embl[TT * NN * EMB];
__device__ __nv_bfloat16 g_yh[NN * HC],  g_yl[NN * HC];
__device__ __nv_bfloat16 g_xh[NN * EMB], g_xl[NN * EMB];
__device__ __nv_bfloat16 g_flath[BB * FLATK], g_flatl[BB * FLATK];
#define WOFF_GAT(br,l) (((br)*2+(l))*65536)
#define WOFF_LIN(br,l) (262144 + ((br)*2+(l))*65536)
#define WOFF_FC1       524288
__device__ __nv_bfloat16 g_wh[851968], g_wl[851968];

// ---------------- fp32 -> bf16 hi/lo split ----------------
__global__ void split_f32(const float* __restrict__ src, __nv_bfloat16* __restrict__ hi,
                          __nv_bfloat16* __restrict__ lo, int n4) {
    int i = blockIdx.x * blockDim.x + threadIdx.x;
    if (i >= n4) return;
    float4 v = ((const float4*)src)[i];
    __nv_bfloat16 h0 = __float2bfloat16(v.x), h1 = __float2bfloat16(v.y);
    __nv_bfloat16 h2 = __float2bfloat16(v.z), h3 = __float2bfloat16(v.w);
    __nv_bfloat16 l0 = __float2bfloat16(v.x - __bfloat162float(h0));
    __nv_bfloat16 l1 = __float2bfloat16(v.y - __bfloat162float(h1));
    __nv_bfloat16 l2 = __float2bfloat16(v.z - __bfloat162float(h2));
    __nv_bfloat16 l3 = __float2bfloat16(v.w - __bfloat162float(h3));
    uint32_t* hp = (uint32_t*)hi;
    uint32_t* lp = (uint32_t*)lo;
    hp[i*2]   = (uint32_t)__bfloat16_as_ushort(h0) | ((uint32_t)__bfloat16_as_ushort(h1) << 16);
    hp[i*2+1] = (uint32_t)__bfloat16_as_ushort(h2) | ((uint32_t)__bfloat16_as_ushort(h3) << 16);
    lp[i*2]   = (uint32_t)__bfloat16_as_ushort(l0) | ((uint32_t)__bfloat16_as_ushort(l1) << 16);
    lp[i*2+1] = (uint32_t)__bfloat16_as_ushort(l2) | ((uint32_t)__bfloat16_as_ushort(l3) << 16);
}

// ============================================================================
// bf16x3 HMMA GEMM, pre-split operands. C = A @ W^T (+bias, +relu).
// A/W as bf16 hi/lo [M,K]/[Ntot,K] row-major. Output f32 OR split bf16.
// Same proven R3 mainloop; BM=BN=128, BK=32, 256 threads.
// ============================================================================
#define BKP 40   // smem row stride in bf16

__device__ __forceinline__ void mma16816(float* c, uint32_t a0, uint32_t a1,
                                         uint32_t a2, uint32_t a3,
                                         uint32_t b0, uint32_t b1) {
    asm volatile(
        "mma.sync.aligned.m16n8k16.row.col.f32.bf16.bf16.f32 "
        "{%0,%1,%2,%3}, {%4,%5,%6,%7}, {%8,%9}, {%0,%1,%2,%3};"
        : "+f"(c[0]), "+f"(c[1]), "+f"(c[2]), "+f"(c[3])
        : "r"(a0), "r"(a1), "r"(a2), "r"(a3), "r"(b0), "r"(b1));
}

__global__ __launch_bounds__(256, 1)
void gemm_pre(const __nv_bfloat16* __restrict__ Aph, const __nv_bfloat16* __restrict__ Apl,
              const __nv_bfloat16* __restrict__ Bph, const __nv_bfloat16* __restrict__ Bpl,
              const float* __restrict__ bias,
              float* __restrict__ Cf, __nv_bfloat16* __restrict__ Ch,
              __nv_bfloat16* __restrict__ Cl,
              int M, int Ntot, int K, int relu)
{
    __shared__ __nv_bfloat16 Ah[128][BKP], Al[128][BKP];
    __shared__ __nv_bfloat16 Bh[128][BKP], Bl[128][BKP];

    const int tid  = threadIdx.x;
    const int warp = tid >> 5;
    const int lane = tid & 31;
    const int g    = lane >> 2;
    const int tg   = lane & 3;
    const int wm   = (warp >> 2) * 64;
    const int wn   = (warp & 3) * 32;
    const int bm   = blockIdx.y * 128;
    const int bn   = blockIdx.x * 128;

    // fill indices: idx covers 512 uint4 slots per array (2 per thread)
    const int fr0 = tid >> 2;          // row for i=0 pass uses idx>>2
    const int fj  = (tid & 3) << 3;    // bf16 col offset 0,8,16,24

    float acc[4][4][4];
#pragma unroll
    for (int mi = 0; mi < 4; mi++)
#pragma unroll
        for (int ni = 0; ni < 4; ni++)
#pragma unroll
            for (int q = 0; q < 4; q++) acc[mi][ni][q] = 0.f;

    const uint4 zero4 = make_uint4(0, 0, 0, 0);

    for (int k0 = 0; k0 < K; k0 += 32) {
#pragma unroll
        for (int i = 0; i < 2; i++) {
            int r = fr0 + (i << 6);    // rows 0..127
            int gr = bm + r;
            uint4 vh = zero4, vl = zero4;
            if (gr < M) {
                vh = *(const uint4*)(Aph + (size_t)gr * K + k0 + fj);
                vl = *(const uint4*)(Apl + (size_t)gr * K + k0 + fj);
            }
            *(uint4*)&Ah[r][fj] = vh;
            *(uint4*)&Al[r][fj] = vl;
            uint4 wh = *(const uint4*)(Bph + (size_t)(bn + r) * K + k0 + fj);
            uint4 wl = *(const uint4*)(Bpl + (size_t)(bn + r) * K + k0 + fj);
            *(uint4*)&Bh[r][fj] = wh;
            *(uint4*)&Bl[r][fj] = wl;
        }
        __syncthreads();

#pragma unroll
        for (int ks = 0; ks < 2; ks++) {
            const int kb = ks * 16;
            uint32_t ah[4][4], al[4][4], bh[4][2], bl[4][2];
#pragma unroll
            for (int mi = 0; mi < 4; mi++) {
                int r = wm + mi * 16;
                ah[mi][0] = *(uint32_t*)&Ah[r + g     ][kb + tg * 2];
                ah[mi][1] = *(uint32_t*)&Ah[r + g + 8 ][kb + tg * 2];
                ah[mi][2] = *(uint32_t*)&Ah[r + g     ][kb + tg * 2 + 8];
                ah[mi][3] = *(uint32_t*)&Ah[r + g + 8 ][kb + tg * 2 + 8];
                al[mi][0] = *(uint32_t*)&Al[r + g     ][kb + tg * 2];
                al[mi][1] = *(uint32_t*)&Al[r + g + 8 ][kb + tg * 2];
                al[mi][2] = *(uint32_t*)&Al[r + g     ][kb + tg * 2 + 8];
                al[mi][3] = *(uint32_t*)&Al[r + g + 8 ][kb + tg * 2 + 8];
            }
#pragma unroll
            for (int ni = 0; ni < 4; ni++) {
                int r = wn + ni * 8 + g;
                bh[ni][0] = *(uint32_t*)&Bh[r][kb + tg * 2];
                bh[ni][1] = *(uint32_t*)&Bh[r][kb + tg * 2 + 8];
                bl[ni][0] = *(uint32_t*)&Bl[r][kb + tg * 2];
                bl[ni][1] = *(uint32_t*)&Bl[r][kb + tg * 2 + 8];
            }
#pragma unroll
            for (int mi = 0; mi < 4; mi++)
#pragma unroll
                for (int ni = 0; ni < 4; ni++) {
                    mma16816(acc[mi][ni], ah[mi][0], ah[mi][1], ah[mi][2], ah[mi][3],
                             bh[ni][0], bh[ni][1]);
                    mma16816(acc[mi][ni], ah[mi][0], ah[mi][1], ah[mi][2], ah[mi][3],
                             bl[ni][0], bl[ni][1]);
                    mma16816(acc[mi][ni], al[mi][0], al[mi][1], al[mi][2], al[mi][3],
                             bh[ni][0], bh[ni][1]);
                }
        }
        __syncthreads();
    }

#pragma unroll
    for (int mi = 0; mi < 4; mi++) {
        int r0 = bm + wm + mi * 16 + g;
        int r1 = r0 + 8;
#pragma unroll
        for (int ni = 0; ni < 4; ni++) {
            int cc = bn + wn + ni * 8 + tg * 2;
            float b0 = 0.f, b1 = 0.f;
            if (bias) { b0 = bias[cc]; b1 = bias[cc + 1]; }
            float2 v0 = make_float2(acc[mi][ni][0] + b0, acc[mi][ni][1] + b1);
            float2 v1 = make_float2(acc[mi][ni][2] + b0, acc[mi][ni][3] + b1);
            if (relu) {
                v0.x = fmaxf(v0.x, 0.f); v0.y = fmaxf(v0.y, 0.f);
                v1.x = fmaxf(v1.x, 0.f); v1.y = fmaxf(v1.y, 0.f);
            }
            if (Cf) {
                if (r0 < M) *(float2*)(Cf + (size_t)r0 * Ntot + cc) = v0;
                if (r1 < M) *(float2*)(Cf + (size_t)r1 * Ntot + cc) = v1;
            } else {
#pragma unroll
                for (int hh = 0; hh < 2; hh++) {
                    float2 v = hh ? v1 : v0;
                    int rr = hh ? r1 : r0;
                    if (rr >= M) continue;
                    __nv_bfloat16 h0 = __float2bfloat16(v.x), h1 = __float2bfloat16(v.y);
                    __nv_bfloat16 l0 = __float2bfloat16(v.x - __bfloat162float(h0));
                    __nv_bfloat16 l1 = __float2bfloat16(v.y - __bfloat162float(h1));
                    *(uint32_t*)(Ch + (size_t)rr * Ntot + cc) =
                        (uint32_t)__bfloat16_as_ushort(h0) | ((uint32_t)__bfloat16_as_ushort(h1) << 16);
                    *(uint32_t*)(Cl + (size_t)rr * Ntot + cc) =
                        (uint32_t)__bfloat16_as_ushort(l0) | ((uint32_t)__bfloat16_as_ushort(l1) << 16);
                }
            }
        }
    }
}

// ---------------- CSR build ----------------
__global__ void init_deg() {
    int i = blockIdx.x * blockDim.x + threadIdx.x;
    if (i < NN) g_deg[i] = 1;
}

__global__ void count_deg(const int* __restrict__ dst) {
    int e = blockIdx.x * blockDim.x + threadIdx.x;
    if (e < EE) atomicAdd(&g_deg[dst[e]], 1);
}

// single-pass scan: 1024 threads x 20 elems each
__global__ void scan_deg(int* __restrict__ rowptr) {
    const int C = 20;
    int tid = threadIdx.x;
    int lane = tid & 31, w = tid >> 5;
    int base = tid * C;
    int loc[C];
    int s = 0;
#pragma unroll
    for (int j = 0; j < C; j++) {
        int idx = base + j;
        int v = (idx < NN) ? g_deg[idx] : 0;
        s += v;
        loc[j] = s;
    }
    int x = s;
#pragma unroll
    for (int off = 1; off < 32; off <<= 1) {
        int t = __shfl_up_sync(0xffffffffu, x, off);
        if (lane >= off) x += t;
    }
    __shared__ int wsum[32];
    if (lane == 31) wsum[w] = x;
    __syncthreads();
    if (w == 0) {
        int y = wsum[lane];
#pragma unroll
        for (int off = 1; off < 32; off <<= 1) {
            int t = __shfl_up_sync(0xffffffffu, y, off);
            if (lane >= off) y += t;
        }
        wsum[lane] = y;
    }
    __syncthreads();
    int offset = x - s + (w > 0 ? wsum[w - 1] : 0);
    if (tid == 0) { rowptr[0] = 0; g_wptr[0] = 0; }
#pragma unroll
    for (int j = 0; j < C; j++) {
        int idx = base + j;
        if (idx < NN) {
            int val = offset + loc[j];
            rowptr[idx + 1] = val;
            g_wptr[idx + 1] = val;
        }
    }
}

__global__ void scatter_edges(const int* __restrict__ src, const int* __restrict__ dst,
                              int* __restrict__ csr) {
    int e = blockIdx.x * blockDim.x + threadIdx.x;
    if (e < EE) {
        int pos = atomicAdd(&g_wptr[dst[e]], 1);
        csr[pos] = src[e];
    }
}

__global__ void scatter_self(int* __restrict__ csr) {
    int n = blockIdx.x * blockDim.x + threadIdx.x;
    if (n < NN) {
        int pos = atomicAdd(&g_wptr[n], 1);
        csr[pos] = n;
    }
}

// ---------------- per-node attention scores ----------------
__global__ void attn_scores(const float* __restrict__ h, const float* __restrict__ as_,
                            const float* __restrict__ ad_) {
    int gwarp = (blockIdx.x * blockDim.x + threadIdx.x) >> 5;
    int lane = threadIdx.x & 31;
    if (gwarp >= NN) return;
    const float* hp = h + (size_t)gwarp * HC;
    float aS[4] = {0.f, 0.f, 0.f, 0.f};
    float aD[4] = {0.f, 0.f, 0.f, 0.f};
#pragma unroll
    for (int i = 0; i < 16; i++) {
        int c = lane + 32 * i;
        float v = hp[c];
        int hh = i >> 2;
        aS[hh] += v * as_[c];
        aD[hh] += v * ad_[c];
    }
#pragma unroll
    for (int hh = 0; hh < 4; hh++) {
#pragma unroll
        for (int off = 16; off; off >>= 1) {
            aS[hh] += __shfl_xor_sync(0xffffffffu, aS[hh], off);
            aD[hh] += __shfl_xor_sync(0xffffffffu, aD[hh], off);
        }
    }
    if (lane == 0) {
        float* sp = g_s + gwarp * 8;
        sp[0] = aS[0]; sp[1] = aS[1]; sp[2] = aS[2]; sp[3] = aS[3];
        sp[4] = aD[0]; sp[5] = aD[1]; sp[6] = aD[2]; sp[7] = aD[3];
    }
}

// ---------------- GAT segment softmax + aggregation (R3 block form) -----------
// Only change vs R3: final store emits bf16 hi/lo split.
__global__ void gat_aggregate(const float* __restrict__ h,
                              const int* __restrict__ rowptr, const int* __restrict__ csr,
                              const float* __restrict__ gbias,
                              __nv_bfloat16* __restrict__ yh, __nv_bfloat16* __restrict__ yl) {
    int d = blockIdx.x;
    int tid = threadIdx.x;
    int start = rowptr[d], end = rowptr[d + 1];

    __shared__ float red[128];
    __shared__ float m[4], invsum[4], sdst[4];
    if (tid < 4) sdst[tid] = g_s[d * 8 + 4 + tid];
    __syncthreads();

    float mx[4] = {-1e30f, -1e30f, -1e30f, -1e30f};
    for (int e = start + tid; e < end; e += 128) {
        int sidx = csr[e];
#pragma unroll
        for (int hh = 0; hh < 4; hh++) {
            float l = g_s[sidx * 8 + hh] + sdst[hh];
            l = l > 0.f ? l : 0.2f * l;
            mx[hh] = fmaxf(mx[hh], l);
        }
    }
#pragma unroll
    for (int hh = 0; hh < 4; hh++) {
        red[tid] = mx[hh];
        __syncthreads();
        for (int off = 64; off; off >>= 1) {
            if (tid < off) red[tid] = fmaxf(red[tid], red[tid + off]);
            __syncthreads();
        }
        if (tid == 0) m[hh] = red[0];
        __syncthreads();
    }

    float sm[4] = {0.f, 0.f, 0.f, 0.f};
    for (int e = start + tid; e < end; e += 128) {
        int sidx = csr[e];
#pragma unroll
        for (int hh = 0; hh < 4; hh++) {
            float l = g_s[sidx * 8 + hh] + sdst[hh];
            l = l > 0.f ? l : 0.2f * l;
            sm[hh] += expf(l - m[hh]);
        }
    }
#pragma unroll
    for (int hh = 0; hh < 4; hh++) {
        red[tid] = sm[hh];
        __syncthreads();
        for (int off = 64; off; off >>= 1) {
            if (tid < off) red[tid] += red[tid + off];
            __syncthreads();
        }
        if (tid == 0) invsum[hh] = 1.f / red[0];
        __syncthreads();
    }

    int head = tid >> 5, lane = tid & 31;
    float mh = m[head], inv = invsum[head], sd = sdst[head];
    float acc0 = 0.f, acc1 = 0.f, acc2 = 0.f, acc3 = 0.f;
    for (int e = start; e < end; e++) {
        int sidx = csr[e];
        float l = g_s[sidx * 8 + head] + sd;
        l = l > 0.f ? l : 0.2f * l;
        float alpha = expf(l - mh) * inv;
        const float* hp = h + (size_t)sidx * HC + head * EMB + lane;
        acc0 += alpha * hp[0];
        acc1 += alpha * hp[32];
        acc2 += alpha * hp[64];
        acc3 += alpha * hp[96];
    }
    int bb = head * EMB + lane;
    size_t ob = (size_t)d * HC + bb;
    float vals[4] = {acc0 + gbias[bb], acc1 + gbias[bb + 32],
                     acc2 + gbias[bb + 64], acc3 + gbias[bb + 96]};
#pragma unroll
    for (int q = 0; q < 4; q++) {
        float v = vals[q];
        __nv_bfloat16 hi = __float2bfloat16(v);
        __nv_bfloat16 lo = __float2bfloat16(v - __bfloat162float(hi));
        yh[ob + q * 32] = hi;
        yl[ob + q * 32] = lo;
    }
}

// ---------------- gather clf rows (bf16) into reversed-time flat layout -------
__global__ void gather_clf(const int* __restrict__ clf, int slot) {
    int idx = blockIdx.x * blockDim.x + threadIdx.x;   // BB*64 uint32 pairs
    if (idx >= BB * 64) return;
    int b = idx >> 6, c2 = idx & 63;
    int node = clf[b];
    uint32_t vh = *(const uint32_t*)(g_xh + (size_t)node * EMB + c2 * 2);
    uint32_t vl = *(const uint32_t*)(g_xl + (size_t)node * EMB + c2 * 2);
    *(uint32_t*)(g_flath + (size_t)b * FLATK + slot + c2 * 2) = vh;
    *(uint32_t*)(g_flatl + (size_t)b * FLATK + slot + c2 * 2) = vl;
}

// ---------------- final fc2 ----------------
__global__ void fc2_kernel(const float* __restrict__ W, const float* __restrict__ bias,
                           float* __restrict__ out) {
    int idx = blockIdx.x * blockDim.x + threadIdx.x;
    if (idx >= BB * 2) return;
    int b = idx >> 1, o = idx & 1;
    const float* hp = g_h1 + (size_t)b * EMB;
    const float* wp = W + o * EMB;
    float acc = bias[o];
#pragma unroll 4
    for (int j = 0; j < EMB; j++) acc += hp[j] * wp[j];
    out[idx] = fmaxf(acc, 0.f);
}

// ---------------- host ----------------
extern "C" void kernel_launch(void* const* d_in, const int* in_sizes, int n_in,
                              void* d_out, int out_size) {
    (void)in_sizes; (void)n_in; (void)out_size;
    const float* emb   = (const float*)d_in[0];
    const int*   edges = (const int*)d_in[1];
    const int*   clf   = (const int*)d_in[5];
    const float* gatW[2] = {(const float*)d_in[6],  (const float*)d_in[12]};
    const float* gas[2]  = {(const float*)d_in[7],  (const float*)d_in[13]};
    const float* gad[2]  = {(const float*)d_in[8],  (const float*)d_in[14]};
    const float* gb[2]   = {(const float*)d_in[9],  (const float*)d_in[15]};
    const float* lW[2]   = {(const float*)d_in[10], (const float*)d_in[16]};
    const float* lb[2]   = {(const float*)d_in[11], (const float*)d_in[17]};
    const float* fc1W = (const float*)d_in[18];
    const float* fc1b = (const float*)d_in[19];
    const float* fc2W = (const float*)d_in[20];
    const float* fc2b = (const float*)d_in[21];

    float *h_, *h1_;
    int *rowptr_, *csr_;
    __nv_bfloat16 *embh_, *embl_, *yh_, *yl_, *xh_, *xl_, *flath_, *flatl_, *wh_, *wl_;
    cudaGetSymbolAddress((void**)&h_,      g_h);
    cudaGetSymbolAddress((void**)&h1_,     g_h1);
    cudaGetSymbolAddress((void**)&rowptr_, g_rowptr);
    cudaGetSymbolAddress((void**)&csr_,    g_csr);
    cudaGetSymbolAddress((void**)&embh_,   g_embh);
    cudaGetSymbolAddress((void**)&embl_,   g_embl);
    cudaGetSymbolAddress((void**)&yh_,     g_yh);
    cudaGetSymbolAddress((void**)&yl_,     g_yl);
    cudaGetSymbolAddress((void**)&xh_,     g_xh);
    cudaGetSymbolAddress((void**)&xl_,     g_xl);
    cudaGetSymbolAddress((void**)&flath_,  g_flath);
    cudaGetSymbolAddress((void**)&flatl_,  g_flatl);
    cudaGetSymbolAddress((void**)&wh_,     g_wh);
    cudaGetSymbolAddress((void**)&wl_,     g_wl);

    auto split = [&](const float* src, __nv_bfloat16* hi, __nv_bfloat16* lo, int n) {
        int n4 = n / 4;
        split_f32<<<(n4 + 255) / 256, 256>>>(src, hi, lo, n4);
    };

    // one-time conversions
    split(emb, embh_, embl_, TT * NN * EMB);
    for (int br = 0; br < 2; br++)
        for (int l = 0; l < LAYERS; l++) {
            split(gatW[br] + (size_t)l * HC * EMB, wh_ + WOFF_GAT(br, l), wl_ + WOFF_GAT(br, l), HC * EMB);
            split(lW[br]   + (size_t)l * EMB * HC, wh_ + WOFF_LIN(br, l), wl_ + WOFF_LIN(br, l), EMB * HC);
        }
    split(fc1W, wh_ + WOFF_FC1, wl_ + WOFF_FC1, EMB * FLATK);

    // build CSR per timestep
    for (int t = 0; t < TT; t++) {
        const int* src = edges + (size_t)t * 2 * EE;
        const int* dst = src + EE;
        init_deg<<<(NN + 255) / 256, 256>>>();
        count_deg<<<(EE + 255) / 256, 256>>>(dst);
        scan_deg<<<1, 1024>>>(rowptr_ + t * (NN + 1));
        scatter_edges<<<(EE + 255) / 256, 256>>>(src, dst, csr_ + (size_t)t * ETOT);
        scatter_self<<<(NN + 255) / 256, 256>>>(csr_ + (size_t)t * ETOT);
    }

    const int MY = (NN + 127) / 128;  // 157
    for (int br = 0; br < 2; br++) {
        for (int t = 0; t < TT; t++) {
            const __nv_bfloat16* ah = embh_ + (size_t)t * NN * EMB;
            const __nv_bfloat16* al = embl_ + (size_t)t * NN * EMB;
            for (int l = 0; l < LAYERS; l++) {
                // h = x @ gatW^T  [N,512] f32
                gemm_pre<<<dim3(HC / 128, MY), 256>>>(
                    ah, al, wh_ + WOFF_GAT(br, l), wl_ + WOFF_GAT(br, l),
                    nullptr, h_, nullptr, nullptr, NN, HC, EMB, 0);
                attn_scores<<<(NN * 32 + 255) / 256, 256>>>(
                    h_, gas[br] + l * HC, gad[br] + l * HC);
                gat_aggregate<<<NN, 128>>>(
                    h_, rowptr_ + t * (NN + 1), csr_ + (size_t)t * ETOT,
                    gb[br] + l * HC, yh_, yl_);
                // x = relu(y @ lW^T + lb) -> bf16 split
                gemm_pre<<<dim3(EMB / 128, MY), 256>>>(
                    yh_, yl_, wh_ + WOFF_LIN(br, l), wl_ + WOFF_LIN(br, l),
                    lb[br] + l * EMB, nullptr, xh_, xl_, NN, EMB, HC, 1);
                ah = xh_; al = xl_;
            }
            gather_clf<<<(BB * 64 + 255) / 256, 256>>>(clf, (TT - 1 - t) * 256 + br * EMB);
        }
    }

    // head MLP
    gemm_pre<<<dim3(1, BB / 128), 256>>>(
        flath_, flatl_, wh_ + WOFF_FC1, wl_ + WOFF_FC1,
        fc1b, h1_, nullptr, nullptr, BB, EMB, FLATK, 1);
    fc2_kernel<<<(BB * 2 + 255) / 256, 256>>>(fc2W, fc2b, (float*)d_out);
}